// round 16
// baseline (speedup 1.0000x reference)
#include <cuda_runtime.h>
#include <cuda_bf16.h>
#include <cuda_fp16.h>
#include <cstdint>

#define Ss  2048
#define Dd  1024
#define Hh  16
#define BH  64
#define BSz 8192

typedef __nv_bfloat16 bf16;

// Scratch (__device__ globals; no allocation)
__device__ bf16 g_Qhi[(size_t)BH * Ss * 64];
__device__ bf16 g_Qlo[(size_t)BH * Ss * 64];
__device__ bf16 g_Khi[(size_t)BH * Ss * 64];
__device__ bf16 g_Klo[(size_t)BH * Ss * 64];
__device__ bf16 g_Vhi[(size_t)BH * Ss * 64];   // holds fp16 bits for V
__device__ float g_ctx[(size_t)BSz * Dd];
__device__ float g_rowsum[(size_t)BH * Ss];
__device__ __half g_e[(size_t)BH * Ss * Ss];   // unnormalized exp(logits), fp16

// ---------------------------------------------------------------------------
__device__ __forceinline__ uint32_t s2u(const void* p) {
    uint32_t a;
    asm("{ .reg .u64 t; cvta.to.shared.u64 t, %1; cvt.u32.u64 %0, t; }"
        : "=r"(a) : "l"(p));
    return a;
}
__device__ __forceinline__ void cp16(void* dst, const void* src) {
    asm volatile("cp.async.cg.shared.global [%0], [%1], 16;"
                 :: "r"(s2u(dst)), "l"(src));
}
#define CP_COMMIT() asm volatile("cp.async.commit_group;")
#define CP_WAIT(n)  asm volatile("cp.async.wait_group %0;" :: "n"(n))

__device__ __forceinline__ void ldsm4(uint32_t r[4], uint32_t a) {
    asm volatile("ldmatrix.sync.aligned.m8n8.x4.shared.b16 {%0,%1,%2,%3}, [%4];"
                 : "=r"(r[0]), "=r"(r[1]), "=r"(r[2]), "=r"(r[3]) : "r"(a));
}
__device__ __forceinline__ void ldsm4t(uint32_t r[4], uint32_t a) {
    asm volatile("ldmatrix.sync.aligned.m8n8.x4.trans.shared.b16 {%0,%1,%2,%3}, [%4];"
                 : "=r"(r[0]), "=r"(r[1]), "=r"(r[2]), "=r"(r[3]) : "r"(a));
}

__device__ __forceinline__ uint32_t pack_bf2(bf16 a, bf16 b) {
    return (uint32_t)__bfloat16_as_ushort(a) | ((uint32_t)__bfloat16_as_ushort(b) << 16);
}
__device__ __forceinline__ uint32_t pack_hf2(__half a, __half b) {
    return (uint32_t)__half_as_ushort(a) | ((uint32_t)__half_as_ushort(b) << 16);
}
__device__ __forceinline__ void split1(float x, bf16& h, bf16& l) {
    h = __float2bfloat16(x);
    l = __float2bfloat16(x - __bfloat162float(h));
}
__device__ __forceinline__ void splith(float x, __half& h, __half& l) {
    h = __float2half_rn(x);
    l = __float2half_rn(x - __half2float(h));
}
__device__ __forceinline__ void mma_bf16(float c[4], const uint32_t a[4], const uint32_t b[2]) {
    asm volatile(
        "mma.sync.aligned.m16n8k16.row.col.f32.bf16.bf16.f32 "
        "{%0,%1,%2,%3}, {%4,%5,%6,%7}, {%8,%9}, {%0,%1,%2,%3};"
        : "+f"(c[0]), "+f"(c[1]), "+f"(c[2]), "+f"(c[3])
        : "r"(a[0]), "r"(a[1]), "r"(a[2]), "r"(a[3]), "r"(b[0]), "r"(b[1]));
}
__device__ __forceinline__ void mma_f16(float c[4], const uint32_t a[4], const uint32_t b[2]) {
    asm volatile(
        "mma.sync.aligned.m16n8k16.row.col.f32.f16.f16.f32 "
        "{%0,%1,%2,%3}, {%4,%5,%6,%7}, {%8,%9}, {%0,%1,%2,%3};"
        : "+f"(c[0]), "+f"(c[1]), "+f"(c[2]), "+f"(c[3])
        : "r"(a[0]), "r"(a[1]), "r"(a[2]), "r"(a[3]), "r"(b[0]), "r"(b[1]));
}

// ---------------------------------------------------------------------------
// proj_k (R13 math, depth-2 LDG prefetch): Y = X @ W + bias.
// 512 thr, 128x128 tile, split-bf16 3-chain MMA.
// DENSE=0: head-split outputs (V as fp16 hi only); DENSE=1: fp32 [M,1024].
// ---------------------------------------------------------------------------
template <int DENSE>
__global__ void __launch_bounds__(512, 1)
proj_k(const float* __restrict__ X0, const float* __restrict__ X1,
       const float* __restrict__ X2,
       const float* __restrict__ W0, const float* __restrict__ W1,
       const float* __restrict__ W2,
       const float* __restrict__ B0, const float* __restrict__ B1,
       const float* __restrict__ B2,
       bf16* __restrict__ H0, bf16* __restrict__ L0,
       bf16* __restrict__ H1, bf16* __restrict__ L1,
       bf16* __restrict__ H2,
       float* __restrict__ OUT)
{
    const int z = blockIdx.z;
    const float* X  = z == 0 ? X0 : z == 1 ? X1 : X2;
    const float* W  = z == 0 ? W0 : z == 1 ? W1 : W2;
    const float* Bi = z == 0 ? B0 : z == 1 ? B1 : B2;
    bf16* Hd = z == 0 ? H0 : z == 1 ? H1 : H2;
    bf16* Ld = z == 0 ? L0 : L1;   // unused for z==2

    __shared__ __align__(16) bf16 As[2][2][128][24];
    __shared__ __align__(16) bf16 Bs[2][2][16][136];

    const int tid = threadIdx.x, lane = tid & 31, warp = tid >> 5;
    const int g = lane >> 2, t = lane & 3;
    const int qd = lane >> 3, rr = lane & 7;
    const int wm = warp >> 2, wn = warp & 3;
    const int bm = blockIdx.y * 128, bn = blockIdx.x * 128;

    const int ar = tid >> 2, ac = tid & 3;
    const int br = tid >> 5, bc = (tid & 31) * 4;

    float acc[2][4][4] = {};

    // depth-2 register prefetch
    float4 axr[2], bxr[2];
    axr[0] = *(const float4*)(X + (size_t)(bm + ar) * 1024 + ac * 4);
    bxr[0] = *(const float4*)(W + (size_t)br * 1024 + bn + bc);
    axr[1] = *(const float4*)(X + (size_t)(bm + ar) * 1024 + 16 + ac * 4);
    bxr[1] = *(const float4*)(W + (size_t)(16 + br) * 1024 + bn + bc);

    for (int it = 0; it < 64; ++it) {
        const int s = it & 1;
        {
            const float4 ax = axr[s];
            const float4 bx = bxr[s];
            bf16 h0, h1, h2, h3, l0, l1, l2, l3;
            split1(ax.x, h0, l0); split1(ax.y, h1, l1);
            split1(ax.z, h2, l2); split1(ax.w, h3, l3);
            *(uint2*)&As[s][0][ar][ac * 4] = make_uint2(pack_bf2(h0, h1), pack_bf2(h2, h3));
            *(uint2*)&As[s][1][ar][ac * 4] = make_uint2(pack_bf2(l0, l1), pack_bf2(l2, l3));
            split1(bx.x, h0, l0); split1(bx.y, h1, l1);
            split1(bx.z, h2, l2); split1(bx.w, h3, l3);
            *(uint2*)&Bs[s][0][br][bc] = make_uint2(pack_bf2(h0, h1), pack_bf2(h2, h3));
            *(uint2*)&Bs[s][1][br][bc] = make_uint2(pack_bf2(l0, l1), pack_bf2(l2, l3));
        }
        if (it + 2 < 64) {
            const int k0 = (it + 2) * 16;
            axr[s] = *(const float4*)(X + (size_t)(bm + ar) * 1024 + k0 + ac * 4);
            bxr[s] = *(const float4*)(W + (size_t)(k0 + br) * 1024 + bn + bc);
        }
        __syncthreads();

        uint32_t af[2][2][4];
#pragma unroll
        for (int mt = 0; mt < 2; mt++)
#pragma unroll
            for (int hl = 0; hl < 2; hl++)
                ldsm4(af[mt][hl],
                      s2u(&As[s][hl][wm * 32 + mt * 16 + (qd & 1) * 8 + rr][(qd >> 1) * 8]));

        uint32_t bfr[4][2][2];
#pragma unroll
        for (int np = 0; np < 2; np++)
#pragma unroll
            for (int hl = 0; hl < 2; hl++) {
                uint32_t bt[4];
                ldsm4t(bt, s2u(&Bs[s][hl][(qd & 1) * 8 + rr]
                                        [wn * 32 + np * 16 + (qd >> 1) * 8]));
                bfr[np * 2][hl][0]     = bt[0];
                bfr[np * 2][hl][1]     = bt[1];
                bfr[np * 2 + 1][hl][0] = bt[2];
                bfr[np * 2 + 1][hl][1] = bt[3];
            }
#pragma unroll
        for (int mt = 0; mt < 2; mt++)
#pragma unroll
            for (int nt = 0; nt < 4; nt++) {
                mma_bf16(acc[mt][nt], af[mt][0], bfr[nt][0]);
                mma_bf16(acc[mt][nt], af[mt][0], bfr[nt][1]);
                mma_bf16(acc[mt][nt], af[mt][1], bfr[nt][0]);
            }
    }

#pragma unroll
    for (int mt = 0; mt < 2; mt++) {
        const int row0 = bm + wm * 32 + mt * 16 + g;
#pragma unroll
        for (int nt = 0; nt < 4; nt++) {
            const int col = bn + wn * 32 + nt * 8 + 2 * t;
            const float b0 = Bi[col], b1 = Bi[col + 1];
            const float v00 = acc[mt][nt][0] + b0, v01 = acc[mt][nt][1] + b1;
            const float v10 = acc[mt][nt][2] + b0, v11 = acc[mt][nt][3] + b1;
            if (DENSE) {
                *(float2*)(OUT + (size_t)row0 * 1024 + col)       = make_float2(v00, v01);
                *(float2*)(OUT + (size_t)(row0 + 8) * 1024 + col) = make_float2(v10, v11);
            } else {
                const int hh = col >> 6, dc = col & 63;
                const int b_ = row0 >> 11;
                const size_t o0 = (((size_t)b_ * 16 + hh) * 2048 + (row0 & 2047)) * 64 + dc;
                const size_t o1 = (((size_t)b_ * 16 + hh) * 2048 + ((row0 + 8) & 2047)) * 64 + dc;
                if (z == 2) {   // V: fp16 hi only (ctx reads only hi)
                    *(uint32_t*)&Hd[o0] = pack_hf2(__float2half_rn(v00), __float2half_rn(v01));
                    *(uint32_t*)&Hd[o1] = pack_hf2(__float2half_rn(v10), __float2half_rn(v11));
                } else {        // Q/K: bf16 hi/lo
                    bf16 h0, l0, h1, l1;
                    split1(v00, h0, l0); split1(v01, h1, l1);
                    *(uint32_t*)&Hd[o0] = pack_bf2(h0, h1);
                    *(uint32_t*)&Ld[o0] = pack_bf2(l0, l1);
                    split1(v10, h0, l0); split1(v11, h1, l1);
                    *(uint32_t*)&Hd[o1] = pack_bf2(h0, h1);
                    *(uint32_t*)&Ld[o1] = pack_bf2(l0, l1);
                }
            }
        }
    }
}

// ---------------------------------------------------------------------------
// logits_k (R13, known-good): Q resident; 16 K-tiles double-buffered.
// ---------------------------------------------------------------------------
#define LG_SMEM 110592

__global__ void __launch_bounds__(512, 1)
logits_k(const bf16* __restrict__ Qhi, const bf16* __restrict__ Qlo,
         const bf16* __restrict__ Khi, const bf16* __restrict__ Klo,
         const float* __restrict__ mask, __half* __restrict__ E,
         float* __restrict__ rowsum)
{
    extern __shared__ bf16 dyn[];
    __shared__ float red[128];

    const int bh = blockIdx.y, b = bh >> 4;
    const int bm = blockIdx.x * 128;
    const int tid = threadIdx.x, lane = tid & 31, warp = tid >> 5;
    const int g = lane >> 2, t = lane & 3;
    const int qd = lane >> 3, rr = lane & 7;
    const int wm = warp >> 2, wn = warp & 3;

    if (tid < 128) red[tid] = 0.f;

    auto loadQ = [&]() {
#pragma unroll
        for (int j = 0; j < 4; j++) {
            const int id = j * 512 + tid;
            const int pl = id >> 10, r = (id >> 3) & 127, ch = id & 7;
            const bf16* src = (pl ? Qlo : Qhi) + ((size_t)bh * 2048 + bm + r) * 64 + ch * 8;
            cp16(dyn + pl * 9216 + r * 72 + ch * 8, src);
        }
    };
    auto loadK = [&](int buf, int jt) {
        const int bn = jt * 128;
#pragma unroll
        for (int j = 0; j < 4; j++) {
            const int id = j * 512 + tid;
            const int pl = id >> 10, r = (id >> 3) & 127, ch = id & 7;
            const bf16* src = (pl ? Klo : Khi) + ((size_t)bh * 2048 + bn + r) * 64 + ch * 8;
            cp16(dyn + 18432 + buf * 18432 + pl * 9216 + r * 72 + ch * 8, src);
        }
    };

    loadQ(); loadK(0, 0); CP_COMMIT();
    loadK(1, 1); CP_COMMIT();

    float rs[2][2] = {};

    for (int jt = 0; jt < 16; ++jt) {
        if (jt < 15) { CP_WAIT(1); } else { CP_WAIT(0); }
        __syncthreads();

        const bf16* Kb = dyn + 18432 + (jt & 1) * 18432;

        float acc[2][4][4] = {};
#pragma unroll
        for (int kc = 0; kc < 64; kc += 16) {
            uint32_t af[2][2][4];
#pragma unroll
            for (int mt = 0; mt < 2; mt++)
#pragma unroll
                for (int hl = 0; hl < 2; hl++)
                    ldsm4(af[mt][hl],
                          s2u(dyn + hl * 9216 +
                              (wm * 32 + mt * 16 + (qd & 1) * 8 + rr) * 72 +
                              kc + (qd >> 1) * 8));

            uint32_t bfr[4][2][2];
#pragma unroll
            for (int np = 0; np < 2; np++)
#pragma unroll
                for (int hl = 0; hl < 2; hl++) {
                    uint32_t bt[4];
                    ldsm4(bt, s2u(Kb + hl * 9216 +
                                  (wn * 32 + np * 16 + (qd >> 1) * 8 + rr) * 72 +
                                  kc + (qd & 1) * 8));
                    bfr[np * 2][hl][0]     = bt[0];
                    bfr[np * 2][hl][1]     = bt[1];
                    bfr[np * 2 + 1][hl][0] = bt[2];
                    bfr[np * 2 + 1][hl][1] = bt[3];
                }
#pragma unroll
            for (int mt = 0; mt < 2; mt++)
#pragma unroll
                for (int nt = 0; nt < 4; nt++) {
                    mma_bf16(acc[mt][nt], af[mt][0], bfr[nt][0]);
                    mma_bf16(acc[mt][nt], af[mt][0], bfr[nt][1]);
                    mma_bf16(acc[mt][nt], af[mt][1], bfr[nt][0]);
                }
        }

        __syncthreads();
        if (jt + 2 < 16) { loadK(jt & 1, jt + 2); CP_COMMIT(); }

        const int bn = jt * 128;
#pragma unroll
        for (int mt = 0; mt < 2; mt++) {
            const int rl0 = wm * 32 + mt * 16 + g;
#pragma unroll
            for (int nt = 0; nt < 4; nt++) {
                const int cl = wn * 32 + nt * 8 + 2 * t;
                const int gc = bn + cl;
                const float mk0 = mask[(size_t)b * 2048 + gc] * -1e9f;
                const float mk1 = mask[(size_t)b * 2048 + gc + 1] * -1e9f;
                const float e00 = __expf(acc[mt][nt][0] * 0.125f + mk0);
                const float e01 = __expf(acc[mt][nt][1] * 0.125f + mk1);
                const float e10 = __expf(acc[mt][nt][2] * 0.125f + mk0);
                const float e11 = __expf(acc[mt][nt][3] * 0.125f + mk1);
                __stcs((__half2*)(E + ((size_t)bh * 2048 + bm + rl0) * 2048 + gc),
                       __floats2half2_rn(e00, e01));
                __stcs((__half2*)(E + ((size_t)bh * 2048 + bm + rl0 + 8) * 2048 + gc),
                       __floats2half2_rn(e10, e11));
                rs[mt][0] += e00 + e01;
                rs[mt][1] += e10 + e11;
            }
        }
    }

#pragma unroll
    for (int mt = 0; mt < 2; mt++)
#pragma unroll
        for (int hf = 0; hf < 2; hf++) {
            float v = rs[mt][hf];
            v += __shfl_xor_sync(0xffffffffu, v, 1);
            v += __shfl_xor_sync(0xffffffffu, v, 2);
            if (t == 0) atomicAdd(&red[wm * 32 + mt * 16 + hf * 8 + g], v);
        }
    __syncthreads();
    if (tid < 128) rowsum[(size_t)bh * 2048 + bm + tid] = red[tid];
}

// ---------------------------------------------------------------------------
// ctx_k (R13, known-good): E + V(hi fp16) via 8-stage cp.async ring.
// ---------------------------------------------------------------------------
#define CTX_STAGES 8
#define CTX_SMEM (CTX_STAGES * 128 * 24 * 2 + CTX_STAGES * 16 * 72 * 2)  // 67584

__global__ void __launch_bounds__(256, 3)
ctx_k(const __half* __restrict__ E, const __half* __restrict__ Vhi,
      const float* __restrict__ rowsum, float* __restrict__ attn,
      float* __restrict__ ctx)
{
    extern __shared__ __align__(16) __half smh[];
    __half (*As)[128][24] = (__half(*)[128][24])smh;
    __half (*Vs)[16][72]  = (__half(*)[16][72])(smh + CTX_STAGES * 128 * 24);

    const int bh = blockIdx.z, b = bh >> 4, h = bh & 15;
    const int bm = blockIdx.x * 128;
    const int tid = threadIdx.x, lane = tid & 31, warp = tid >> 5;
    const int g = lane >> 2, t = lane & 3;
    const int qd = lane >> 3, rr = lane & 7;
    const int wm = warp >> 1, wn = warp & 1;

    const int lr = tid >> 1, lc = tid & 1;
    const __half* Ebase = E + ((size_t)bh * 2048 + bm + lr) * 2048 + lc * 8;
    const int vkr = (tid & 127) >> 3, vch = tid & 7;
    const __half* Vbase = Vhi + ((size_t)bh * 2048 + vkr) * 64 + vch * 8;

    const float inv = 1.f / rowsum[(size_t)bh * 2048 + bm + lr];
    float* Arow = attn + ((size_t)bh * 2048 + bm + lr) * 2048 + lc * 8;

#define LOAD_STAGE(st, it_) do {                                       \
        cp16(&As[st][lr][lc * 8], Ebase + (size_t)(it_) * 16);         \
        if (tid < 128)                                                 \
            cp16(&Vs[st][vkr][vch * 8], Vbase + (size_t)(it_) * 1024); \
        CP_COMMIT();                                                   \
    } while (0)

#pragma unroll
    for (int p = 0; p < CTX_STAGES - 1; ++p) LOAD_STAGE(p, p);

    float acc[2][4][4] = {};

    for (int it = 0; it < 128; ++it) {
        const int st = it % CTX_STAGES;
        if (it + CTX_STAGES - 1 < 128) { CP_WAIT(CTX_STAGES - 2); } else { CP_WAIT(0); }
        __syncthreads();
        if (it + CTX_STAGES - 1 < 128)
            LOAD_STAGE((it + CTX_STAGES - 1) % CTX_STAGES, it + CTX_STAGES - 1);

        {
            const uint4 ev = *(const uint4*)&As[st][lr][lc * 8];
            const __half2* h2 = (const __half2*)&ev;
            float p[8];
#pragma unroll
            for (int q = 0; q < 4; q++) {
                float2 f = __half22float2(h2[q]);
                p[2 * q]     = f.x * inv;
                p[2 * q + 1] = f.y * inv;
            }
            __stcs((float4*)(Arow + it * 16),     make_float4(p[0], p[1], p[2], p[3]));
            __stcs((float4*)(Arow + it * 16 + 4), make_float4(p[4], p[5], p[6], p[7]));
        }

        uint32_t af[2][4];
#pragma unroll
        for (int mt = 0; mt < 2; mt++)
            ldsm4(af[mt],
                  s2u(&As[st][wm * 32 + mt * 16 + (qd & 1) * 8 + rr][(qd >> 1) * 8]));

        uint32_t bfr[4][2];
#pragma unroll
        for (int np = 0; np < 2; np++) {
            uint32_t bt[4];
            ldsm4t(bt, s2u(&Vs[st][(qd & 1) * 8 + rr]
                                  [wn * 32 + np * 16 + (qd >> 1) * 8]));
            bfr[np * 2][0]     = bt[0];
            bfr[np * 2][1]     = bt[1];
            bfr[np * 2 + 1][0] = bt[2];
            bfr[np * 2 + 1][1] = bt[3];
        }
#pragma unroll
        for (int mt = 0; mt < 2; mt++)
#pragma unroll
            for (int nt = 0; nt < 4; nt++)
                mma_f16(acc[mt][nt], af[mt], bfr[nt]);
    }
#undef LOAD_STAGE

#pragma unroll
    for (int mt = 0; mt < 2; mt++) {
        const int row0 = bm + wm * 32 + mt * 16 + g;
        const float i0 = 1.f / rowsum[(size_t)bh * 2048 + row0];
        const float i1 = 1.f / rowsum[(size_t)bh * 2048 + row0 + 8];
#pragma unroll
        for (int nt = 0; nt < 4; nt++) {
            const int col = wn * 32 + nt * 8 + 2 * t;
            *(float2*)(ctx + ((size_t)b * 2048 + row0) * 1024 + h * 64 + col) =
                make_float2(acc[mt][nt][0] * i0, acc[mt][nt][1] * i0);
            *(float2*)(ctx + ((size_t)b * 2048 + row0 + 8) * 1024 + h * 64 + col) =
                make_float2(acc[mt][nt][2] * i1, acc[mt][nt][3] * i1);
        }
    }
}

// ---------------------------------------------------------------------------
extern "C" void kernel_launch(void* const* d_in, const int* in_sizes, int n_in,
                              void* d_out, int out_size)
{
    const float* q    = (const float*)d_in[0];
    const float* k    = (const float*)d_in[1];
    const float* v    = (const float*)d_in[2];
    const float* mask = (const float*)d_in[3];
    const float* Wq   = (const float*)d_in[4];
    const float* bq   = (const float*)d_in[5];
    const float* Wk   = (const float*)d_in[6];
    const float* bk   = (const float*)d_in[7];
    const float* Wv   = (const float*)d_in[8];
    const float* bv   = (const float*)d_in[9];
    const float* Wo   = (const float*)d_in[10];
    const float* bo   = (const float*)d_in[11];

    float* out  = (float*)d_out;
    float* attn = out + (size_t)BSz * Dd;

    bf16 *Qhi, *Qlo, *Khi, *Klo, *Vhi;
    float *ctxp, *rowsum;
    __half* E;
    cudaGetSymbolAddress((void**)&Qhi, g_Qhi);
    cudaGetSymbolAddress((void**)&Qlo, g_Qlo);
    cudaGetSymbolAddress((void**)&Khi, g_Khi);
    cudaGetSymbolAddress((void**)&Klo, g_Klo);
    cudaGetSymbolAddress((void**)&Vhi, g_Vhi);
    cudaGetSymbolAddress((void**)&ctxp, g_ctx);
    cudaGetSymbolAddress((void**)&rowsum, g_rowsum);
    cudaGetSymbolAddress((void**)&E, g_e);

    cudaFuncSetAttribute(logits_k, cudaFuncAttributeMaxDynamicSharedMemorySize, LG_SMEM);
    cudaFuncSetAttribute(ctx_k, cudaFuncAttributeMaxDynamicSharedMemorySize, CTX_SMEM);

    proj_k<0><<<dim3(8, 64, 3), 512>>>(q, k, v, Wq, Wk, Wv, bq, bk, bv,
                                       Qhi, Qlo, Khi, Klo, Vhi, nullptr);

    logits_k<<<dim3(16, 64), 512, LG_SMEM>>>(Qhi, Qlo, Khi, Klo, mask, E, rowsum);

    ctx_k<<<dim3(16, 1, 64), 256, CTX_SMEM>>>(E, (const __half*)Vhi,
                                              rowsum, attn, ctxp);

    proj_k<1><<<dim3(8, 64, 1), 512>>>(ctxp, ctxp, ctxp, Wo, Wo, Wo, bo, bo, bo,
                                       nullptr, nullptr, nullptr, nullptr,
                                       nullptr, out);
}

// round 17
// speedup vs baseline: 1.2717x; 1.2717x over previous
#include <cuda_runtime.h>
#include <cuda_bf16.h>
#include <cuda_fp16.h>
#include <cstdint>

#define Ss  2048
#define Dd  1024
#define Hh  16
#define BH  64
#define BSz 8192

typedef __nv_bfloat16 bf16;

// Scratch (__device__ globals; no allocation)
__device__ bf16 g_Qhi[(size_t)BH * Ss * 64];
__device__ bf16 g_Qlo[(size_t)BH * Ss * 64];
__device__ bf16 g_Khi[(size_t)BH * Ss * 64];
__device__ bf16 g_Klo[(size_t)BH * Ss * 64];
__device__ bf16 g_Vhi[(size_t)BH * Ss * 64];   // holds fp16 bits for V
__device__ float g_ctx[(size_t)BSz * Dd];
__device__ float g_rowsum[(size_t)BH * Ss];
__device__ __half g_e[(size_t)BH * Ss * Ss];   // unnormalized exp(logits), fp16

// ---------------------------------------------------------------------------
__device__ __forceinline__ uint32_t s2u(const void* p) {
    uint32_t a;
    asm("{ .reg .u64 t; cvta.to.shared.u64 t, %1; cvt.u32.u64 %0, t; }"
        : "=r"(a) : "l"(p));
    return a;
}
__device__ __forceinline__ void cp16(void* dst, const void* src) {
    asm volatile("cp.async.cg.shared.global [%0], [%1], 16;"
                 :: "r"(s2u(dst)), "l"(src));
}
#define CP_COMMIT() asm volatile("cp.async.commit_group;")
#define CP_WAIT(n)  asm volatile("cp.async.wait_group %0;" :: "n"(n))

__device__ __forceinline__ void ldsm4(uint32_t r[4], uint32_t a) {
    asm volatile("ldmatrix.sync.aligned.m8n8.x4.shared.b16 {%0,%1,%2,%3}, [%4];"
                 : "=r"(r[0]), "=r"(r[1]), "=r"(r[2]), "=r"(r[3]) : "r"(a));
}
__device__ __forceinline__ void ldsm4t(uint32_t r[4], uint32_t a) {
    asm volatile("ldmatrix.sync.aligned.m8n8.x4.trans.shared.b16 {%0,%1,%2,%3}, [%4];"
                 : "=r"(r[0]), "=r"(r[1]), "=r"(r[2]), "=r"(r[3]) : "r"(a));
}

__device__ __forceinline__ uint32_t pack_bf2(bf16 a, bf16 b) {
    return (uint32_t)__bfloat16_as_ushort(a) | ((uint32_t)__bfloat16_as_ushort(b) << 16);
}
__device__ __forceinline__ uint32_t pack_hf2(__half a, __half b) {
    return (uint32_t)__half_as_ushort(a) | ((uint32_t)__half_as_ushort(b) << 16);
}
__device__ __forceinline__ void split1(float x, bf16& h, bf16& l) {
    h = __float2bfloat16(x);
    l = __float2bfloat16(x - __bfloat162float(h));
}
__device__ __forceinline__ void mma_bf16(float c[4], const uint32_t a[4], const uint32_t b[2]) {
    asm volatile(
        "mma.sync.aligned.m16n8k16.row.col.f32.bf16.bf16.f32 "
        "{%0,%1,%2,%3}, {%4,%5,%6,%7}, {%8,%9}, {%0,%1,%2,%3};"
        : "+f"(c[0]), "+f"(c[1]), "+f"(c[2]), "+f"(c[3])
        : "r"(a[0]), "r"(a[1]), "r"(a[2]), "r"(a[3]), "r"(b[0]), "r"(b[1]));
}
__device__ __forceinline__ void mma_f16(float c[4], const uint32_t a[4], const uint32_t b[2]) {
    asm volatile(
        "mma.sync.aligned.m16n8k16.row.col.f32.f16.f16.f32 "
        "{%0,%1,%2,%3}, {%4,%5,%6,%7}, {%8,%9}, {%0,%1,%2,%3};"
        : "+f"(c[0]), "+f"(c[1]), "+f"(c[2]), "+f"(c[3])
        : "r"(a[0]), "r"(a[1]), "r"(a[2]), "r"(a[3]), "r"(b[0]), "r"(b[1]));
}

// ---------------------------------------------------------------------------
// proj_k (R13 exact: depth-1 prefetch, split-bf16 3-chain): Y = X @ W + bias.
// DENSE=0: head-split outputs (Q/K bf16 hi/lo, V fp16 hi only); DENSE=1: fp32.
// ---------------------------------------------------------------------------
template <int DENSE>
__global__ void __launch_bounds__(512, 1)
proj_k(const float* __restrict__ X0, const float* __restrict__ X1,
       const float* __restrict__ X2,
       const float* __restrict__ W0, const float* __restrict__ W1,
       const float* __restrict__ W2,
       const float* __restrict__ B0, const float* __restrict__ B1,
       const float* __restrict__ B2,
       bf16* __restrict__ H0, bf16* __restrict__ L0,
       bf16* __restrict__ H1, bf16* __restrict__ L1,
       bf16* __restrict__ H2,
       float* __restrict__ OUT)
{
    const int z = blockIdx.z;
    const float* X  = z == 0 ? X0 : z == 1 ? X1 : X2;
    const float* W  = z == 0 ? W0 : z == 1 ? W1 : W2;
    const float* Bi = z == 0 ? B0 : z == 1 ? B1 : B2;
    bf16* Hd = z == 0 ? H0 : z == 1 ? H1 : H2;
    bf16* Ld = z == 0 ? L0 : L1;   // unused for z==2

    __shared__ __align__(16) bf16 As[2][2][128][24];
    __shared__ __align__(16) bf16 Bs[2][2][16][136];

    const int tid = threadIdx.x, lane = tid & 31, warp = tid >> 5;
    const int g = lane >> 2, t = lane & 3;
    const int qd = lane >> 3, rr = lane & 7;
    const int wm = warp >> 2, wn = warp & 3;
    const int bm = blockIdx.y * 128, bn = blockIdx.x * 128;

    const int ar = tid >> 2, ac = tid & 3;
    const int br = tid >> 5, bc = (tid & 31) * 4;

    float acc[2][4][4] = {};

    float4 ax = *(const float4*)(X + (size_t)(bm + ar) * 1024 + ac * 4);
    float4 bx = *(const float4*)(W + (size_t)br * 1024 + bn + bc);

    for (int it = 0; it < 64; ++it) {
        const int s = it & 1;
        {
            bf16 h0, h1, h2, h3, l0, l1, l2, l3;
            split1(ax.x, h0, l0); split1(ax.y, h1, l1);
            split1(ax.z, h2, l2); split1(ax.w, h3, l3);
            *(uint2*)&As[s][0][ar][ac * 4] = make_uint2(pack_bf2(h0, h1), pack_bf2(h2, h3));
            *(uint2*)&As[s][1][ar][ac * 4] = make_uint2(pack_bf2(l0, l1), pack_bf2(l2, l3));
            split1(bx.x, h0, l0); split1(bx.y, h1, l1);
            split1(bx.z, h2, l2); split1(bx.w, h3, l3);
            *(uint2*)&Bs[s][0][br][bc] = make_uint2(pack_bf2(h0, h1), pack_bf2(h2, h3));
            *(uint2*)&Bs[s][1][br][bc] = make_uint2(pack_bf2(l0, l1), pack_bf2(l2, l3));
        }
        if (it + 1 < 64) {
            const int k0 = (it + 1) * 16;
            ax = *(const float4*)(X + (size_t)(bm + ar) * 1024 + k0 + ac * 4);
            bx = *(const float4*)(W + (size_t)(k0 + br) * 1024 + bn + bc);
        }
        __syncthreads();

        uint32_t af[2][2][4];
#pragma unroll
        for (int mt = 0; mt < 2; mt++)
#pragma unroll
            for (int hl = 0; hl < 2; hl++)
                ldsm4(af[mt][hl],
                      s2u(&As[s][hl][wm * 32 + mt * 16 + (qd & 1) * 8 + rr][(qd >> 1) * 8]));

        uint32_t bfr[4][2][2];
#pragma unroll
        for (int np = 0; np < 2; np++)
#pragma unroll
            for (int hl = 0; hl < 2; hl++) {
                uint32_t bt[4];
                ldsm4t(bt, s2u(&Bs[s][hl][(qd & 1) * 8 + rr]
                                        [wn * 32 + np * 16 + (qd >> 1) * 8]));
                bfr[np * 2][hl][0]     = bt[0];
                bfr[np * 2][hl][1]     = bt[1];
                bfr[np * 2 + 1][hl][0] = bt[2];
                bfr[np * 2 + 1][hl][1] = bt[3];
            }
#pragma unroll
        for (int mt = 0; mt < 2; mt++)
#pragma unroll
            for (int nt = 0; nt < 4; nt++) {
                mma_bf16(acc[mt][nt], af[mt][0], bfr[nt][0]);
                mma_bf16(acc[mt][nt], af[mt][0], bfr[nt][1]);
                mma_bf16(acc[mt][nt], af[mt][1], bfr[nt][0]);
            }
    }

#pragma unroll
    for (int mt = 0; mt < 2; mt++) {
        const int row0 = bm + wm * 32 + mt * 16 + g;
#pragma unroll
        for (int nt = 0; nt < 4; nt++) {
            const int col = bn + wn * 32 + nt * 8 + 2 * t;
            const float b0 = Bi[col], b1 = Bi[col + 1];
            const float v00 = acc[mt][nt][0] + b0, v01 = acc[mt][nt][1] + b1;
            const float v10 = acc[mt][nt][2] + b0, v11 = acc[mt][nt][3] + b1;
            if (DENSE) {
                *(float2*)(OUT + (size_t)row0 * 1024 + col)       = make_float2(v00, v01);
                *(float2*)(OUT + (size_t)(row0 + 8) * 1024 + col) = make_float2(v10, v11);
            } else {
                const int hh = col >> 6, dc = col & 63;
                const int b_ = row0 >> 11;
                const size_t o0 = (((size_t)b_ * 16 + hh) * 2048 + (row0 & 2047)) * 64 + dc;
                const size_t o1 = (((size_t)b_ * 16 + hh) * 2048 + ((row0 + 8) & 2047)) * 64 + dc;
                if (z == 2) {   // V: fp16 hi only (ctx reads only hi)
                    *(uint32_t*)&Hd[o0] = pack_hf2(__float2half_rn(v00), __float2half_rn(v01));
                    *(uint32_t*)&Hd[o1] = pack_hf2(__float2half_rn(v10), __float2half_rn(v11));
                } else {        // Q/K: bf16 hi/lo
                    bf16 h0, l0, h1, l1;
                    split1(v00, h0, l0); split1(v01, h1, l1);
                    *(uint32_t*)&Hd[o0] = pack_bf2(h0, h1);
                    *(uint32_t*)&Ld[o0] = pack_bf2(l0, l1);
                    split1(v10, h0, l0); split1(v11, h1, l1);
                    *(uint32_t*)&Hd[o1] = pack_bf2(h0, h1);
                    *(uint32_t*)&Ld[o1] = pack_bf2(l0, l1);
                }
            }
        }
    }
}

// ---------------------------------------------------------------------------
// logits_k (R13, known-good): Q resident; 16 K-tiles double-buffered.
// ---------------------------------------------------------------------------
#define LG_SMEM 110592

__global__ void __launch_bounds__(512, 1)
logits_k(const bf16* __restrict__ Qhi, const bf16* __restrict__ Qlo,
         const bf16* __restrict__ Khi, const bf16* __restrict__ Klo,
         const float* __restrict__ mask, __half* __restrict__ E,
         float* __restrict__ rowsum)
{
    extern __shared__ bf16 dyn[];
    __shared__ float red[128];

    const int bh = blockIdx.y, b = bh >> 4;
    const int bm = blockIdx.x * 128;
    const int tid = threadIdx.x, lane = tid & 31, warp = tid >> 5;
    const int g = lane >> 2, t = lane & 3;
    const int qd = lane >> 3, rr = lane & 7;
    const int wm = warp >> 2, wn = warp & 3;

    if (tid < 128) red[tid] = 0.f;

    auto loadQ = [&]() {
#pragma unroll
        for (int j = 0; j < 4; j++) {
            const int id = j * 512 + tid;
            const int pl = id >> 10, r = (id >> 3) & 127, ch = id & 7;
            const bf16* src = (pl ? Qlo : Qhi) + ((size_t)bh * 2048 + bm + r) * 64 + ch * 8;
            cp16(dyn + pl * 9216 + r * 72 + ch * 8, src);
        }
    };
    auto loadK = [&](int buf, int jt) {
        const int bn = jt * 128;
#pragma unroll
        for (int j = 0; j < 4; j++) {
            const int id = j * 512 + tid;
            const int pl = id >> 10, r = (id >> 3) & 127, ch = id & 7;
            const bf16* src = (pl ? Klo : Khi) + ((size_t)bh * 2048 + bn + r) * 64 + ch * 8;
            cp16(dyn + 18432 + buf * 18432 + pl * 9216 + r * 72 + ch * 8, src);
        }
    };

    loadQ(); loadK(0, 0); CP_COMMIT();
    loadK(1, 1); CP_COMMIT();

    float rs[2][2] = {};

    for (int jt = 0; jt < 16; ++jt) {
        if (jt < 15) { CP_WAIT(1); } else { CP_WAIT(0); }
        __syncthreads();

        const bf16* Kb = dyn + 18432 + (jt & 1) * 18432;

        float acc[2][4][4] = {};
#pragma unroll
        for (int kc = 0; kc < 64; kc += 16) {
            uint32_t af[2][2][4];
#pragma unroll
            for (int mt = 0; mt < 2; mt++)
#pragma unroll
                for (int hl = 0; hl < 2; hl++)
                    ldsm4(af[mt][hl],
                          s2u(dyn + hl * 9216 +
                              (wm * 32 + mt * 16 + (qd & 1) * 8 + rr) * 72 +
                              kc + (qd >> 1) * 8));

            uint32_t bfr[4][2][2];
#pragma unroll
            for (int np = 0; np < 2; np++)
#pragma unroll
                for (int hl = 0; hl < 2; hl++) {
                    uint32_t bt[4];
                    ldsm4(bt, s2u(Kb + hl * 9216 +
                                  (wn * 32 + np * 16 + (qd >> 1) * 8 + rr) * 72 +
                                  kc + (qd & 1) * 8));
                    bfr[np * 2][hl][0]     = bt[0];
                    bfr[np * 2][hl][1]     = bt[1];
                    bfr[np * 2 + 1][hl][0] = bt[2];
                    bfr[np * 2 + 1][hl][1] = bt[3];
                }
#pragma unroll
            for (int mt = 0; mt < 2; mt++)
#pragma unroll
                for (int nt = 0; nt < 4; nt++) {
                    mma_bf16(acc[mt][nt], af[mt][0], bfr[nt][0]);
                    mma_bf16(acc[mt][nt], af[mt][0], bfr[nt][1]);
                    mma_bf16(acc[mt][nt], af[mt][1], bfr[nt][0]);
                }
        }

        __syncthreads();
        if (jt + 2 < 16) { loadK(jt & 1, jt + 2); CP_COMMIT(); }

        const int bn = jt * 128;
#pragma unroll
        for (int mt = 0; mt < 2; mt++) {
            const int rl0 = wm * 32 + mt * 16 + g;
#pragma unroll
            for (int nt = 0; nt < 4; nt++) {
                const int cl = wn * 32 + nt * 8 + 2 * t;
                const int gc = bn + cl;
                const float mk0 = mask[(size_t)b * 2048 + gc] * -1e9f;
                const float mk1 = mask[(size_t)b * 2048 + gc + 1] * -1e9f;
                const float e00 = __expf(acc[mt][nt][0] * 0.125f + mk0);
                const float e01 = __expf(acc[mt][nt][1] * 0.125f + mk1);
                const float e10 = __expf(acc[mt][nt][2] * 0.125f + mk0);
                const float e11 = __expf(acc[mt][nt][3] * 0.125f + mk1);
                __stcs((__half2*)(E + ((size_t)bh * 2048 + bm + rl0) * 2048 + gc),
                       __floats2half2_rn(e00, e01));
                __stcs((__half2*)(E + ((size_t)bh * 2048 + bm + rl0 + 8) * 2048 + gc),
                       __floats2half2_rn(e10, e11));
                rs[mt][0] += e00 + e01;
                rs[mt][1] += e10 + e11;
            }
        }
    }

#pragma unroll
    for (int mt = 0; mt < 2; mt++)
#pragma unroll
        for (int hf = 0; hf < 2; hf++) {
            float v = rs[mt][hf];
            v += __shfl_xor_sync(0xffffffffu, v, 1);
            v += __shfl_xor_sync(0xffffffffu, v, 2);
            if (t == 0) atomicAdd(&red[wm * 32 + mt * 16 + hf * 8 + g], v);
        }
    __syncthreads();
    if (tid < 128) rowsum[(size_t)bh * 2048 + bm + tid] = red[tid];
}

// ---------------------------------------------------------------------------
// ctx_k (R13, known-good): E + V(hi fp16) via 8-stage cp.async ring.
// ---------------------------------------------------------------------------
#define CTX_STAGES 8
#define CTX_SMEM (CTX_STAGES * 128 * 24 * 2 + CTX_STAGES * 16 * 72 * 2)  // 67584

__global__ void __launch_bounds__(256, 3)
ctx_k(const __half* __restrict__ E, const __half* __restrict__ Vhi,
      const float* __restrict__ rowsum, float* __restrict__ attn,
      float* __restrict__ ctx)
{
    extern __shared__ __align__(16) __half smh[];
    __half (*As)[128][24] = (__half(*)[128][24])smh;
    __half (*Vs)[16][72]  = (__half(*)[16][72])(smh + CTX_STAGES * 128 * 24);

    const int bh = blockIdx.z, b = bh >> 4, h = bh & 15;
    const int bm = blockIdx.x * 128;
    const int tid = threadIdx.x, lane = tid & 31, warp = tid >> 5;
    const int g = lane >> 2, t = lane & 3;
    const int qd = lane >> 3, rr = lane & 7;
    const int wm = warp >> 1, wn = warp & 1;

    const int lr = tid >> 1, lc = tid & 1;
    const __half* Ebase = E + ((size_t)bh * 2048 + bm + lr) * 2048 + lc * 8;
    const int vkr = (tid & 127) >> 3, vch = tid & 7;
    const __half* Vbase = Vhi + ((size_t)bh * 2048 + vkr) * 64 + vch * 8;

    const float inv = 1.f / rowsum[(size_t)bh * 2048 + bm + lr];
    float* Arow = attn + ((size_t)bh * 2048 + bm + lr) * 2048 + lc * 8;

#define LOAD_STAGE(st, it_) do {                                       \
        cp16(&As[st][lr][lc * 8], Ebase + (size_t)(it_) * 16);         \
        if (tid < 128)                                                 \
            cp16(&Vs[st][vkr][vch * 8], Vbase + (size_t)(it_) * 1024); \
        CP_COMMIT();                                                   \
    } while (0)

#pragma unroll
    for (int p = 0; p < CTX_STAGES - 1; ++p) LOAD_STAGE(p, p);

    float acc[2][4][4] = {};

    for (int it = 0; it < 128; ++it) {
        const int st = it % CTX_STAGES;
        if (it + CTX_STAGES - 1 < 128) { CP_WAIT(CTX_STAGES - 2); } else { CP_WAIT(0); }
        __syncthreads();
        if (it + CTX_STAGES - 1 < 128)
            LOAD_STAGE((it + CTX_STAGES - 1) % CTX_STAGES, it + CTX_STAGES - 1);

        {
            const uint4 ev = *(const uint4*)&As[st][lr][lc * 8];
            const __half2* h2 = (const __half2*)&ev;
            float p[8];
#pragma unroll
            for (int q = 0; q < 4; q++) {
                float2 f = __half22float2(h2[q]);
                p[2 * q]     = f.x * inv;
                p[2 * q + 1] = f.y * inv;
            }
            __stcs((float4*)(Arow + it * 16),     make_float4(p[0], p[1], p[2], p[3]));
            __stcs((float4*)(Arow + it * 16 + 4), make_float4(p[4], p[5], p[6], p[7]));
        }

        uint32_t af[2][4];
#pragma unroll
        for (int mt = 0; mt < 2; mt++)
            ldsm4(af[mt],
                  s2u(&As[st][wm * 32 + mt * 16 + (qd & 1) * 8 + rr][(qd >> 1) * 8]));

        uint32_t bfr[4][2];
#pragma unroll
        for (int np = 0; np < 2; np++) {
            uint32_t bt[4];
            ldsm4t(bt, s2u(&Vs[st][(qd & 1) * 8 + rr]
                                  [wn * 32 + np * 16 + (qd >> 1) * 8]));
            bfr[np * 2][0]     = bt[0];
            bfr[np * 2][1]     = bt[1];
            bfr[np * 2 + 1][0] = bt[2];
            bfr[np * 2 + 1][1] = bt[3];
        }
#pragma unroll
        for (int mt = 0; mt < 2; mt++)
#pragma unroll
            for (int nt = 0; nt < 4; nt++)
                mma_f16(acc[mt][nt], af[mt], bfr[nt]);
    }
#undef LOAD_STAGE

#pragma unroll
    for (int mt = 0; mt < 2; mt++) {
        const int row0 = bm + wm * 32 + mt * 16 + g;
        const float i0 = 1.f / rowsum[(size_t)bh * 2048 + row0];
        const float i1 = 1.f / rowsum[(size_t)bh * 2048 + row0 + 8];
#pragma unroll
        for (int nt = 0; nt < 4; nt++) {
            const int col = wn * 32 + nt * 8 + 2 * t;
            *(float2*)(ctx + ((size_t)b * 2048 + row0) * 1024 + h * 64 + col) =
                make_float2(acc[mt][nt][0] * i0, acc[mt][nt][1] * i0);
            *(float2*)(ctx + ((size_t)b * 2048 + row0 + 8) * 1024 + h * 64 + col) =
                make_float2(acc[mt][nt][2] * i1, acc[mt][nt][3] * i1);
        }
    }
}

// ---------------------------------------------------------------------------
extern "C" void kernel_launch(void* const* d_in, const int* in_sizes, int n_in,
                              void* d_out, int out_size)
{
    const float* q    = (const float*)d_in[0];
    const float* k    = (const float*)d_in[1];
    const float* v    = (const float*)d_in[2];
    const float* mask = (const float*)d_in[3];
    const float* Wq   = (const float*)d_in[4];
    const float* bq   = (const float*)d_in[5];
    const float* Wk   = (const float*)d_in[6];
    const float* bk   = (const float*)d_in[7];
    const float* Wv   = (const float*)d_in[8];
    const float* bv   = (const float*)d_in[9];
    const float* Wo   = (const float*)d_in[10];
    const float* bo   = (const float*)d_in[11];

    float* out  = (float*)d_out;
    float* attn = out + (size_t)BSz * Dd;

    bf16 *Qhi, *Qlo, *Khi, *Klo, *Vhi;
    float *ctxp, *rowsum;
    __half* E;
    cudaGetSymbolAddress((void**)&Qhi, g_Qhi);
    cudaGetSymbolAddress((void**)&Qlo, g_Qlo);
    cudaGetSymbolAddress((void**)&Khi, g_Khi);
    cudaGetSymbolAddress((void**)&Klo, g_Klo);
    cudaGetSymbolAddress((void**)&Vhi, g_Vhi);
    cudaGetSymbolAddress((void**)&ctxp, g_ctx);
    cudaGetSymbolAddress((void**)&rowsum, g_rowsum);
    cudaGetSymbolAddress((void**)&E, g_e);

    cudaFuncSetAttribute(logits_k, cudaFuncAttributeMaxDynamicSharedMemorySize, LG_SMEM);
    cudaFuncSetAttribute(ctx_k, cudaFuncAttributeMaxDynamicSharedMemorySize, CTX_SMEM);

    proj_k<0><<<dim3(8, 64, 3), 512>>>(q, k, v, Wq, Wk, Wv, bq, bk, bv,
                                       Qhi, Qlo, Khi, Klo, Vhi, nullptr);

    logits_k<<<dim3(16, 64), 512, LG_SMEM>>>(Qhi, Qlo, Khi, Klo, mask, E, rowsum);

    ctx_k<<<dim3(16, 1, 64), 256, CTX_SMEM>>>(E, (const __half*)Vhi,
                                              rowsum, attn, ctxp);

    proj_k<1><<<dim3(8, 64, 1), 512>>>(ctxp, ctxp, ctxp, Wo, Wo, Wo, bo, bo, bo,
                                       nullptr, nullptr, nullptr, nullptr,
                                       nullptr, out);
}